// round 4
// baseline (speedup 1.0000x reference)
#include <cuda_runtime.h>
#include <math.h>

#define NN 2048
#define DD 256
#define HH 128
#define GG 8
#define MAXD 128
#define NWRD 64   // 32-bit words per adjacency row (2048 bits)

// ---------------- device scratch (static, no runtime allocation) ----------------
static __device__ unsigned g_adj[NN*NWRD];
static __device__ int      g_deg[NN];
static __device__ int      g_nbr[NN*MAXD];
static __device__ int      g_off[NN+1];
static __device__ int      g_nedges;
static __device__ unsigned short g_ecol[32768];   // CSR columns (u16)
static __device__ float    g_V[NN];
static __device__ float    g_ent[NN];
static __device__ float    g_p[NN];
static __device__ float    g_a1[NN];
static __device__ float    g_u[NN*HH];
static __device__ float    g_z[NN*HH];
static __device__ float    g_h[NN*HH];
static __device__ float    g_sc[HH];
static __device__ float    g_sh[HH];
static __device__ float    g_gamma;
static __device__ float    g_loss;
static __device__ unsigned g_sel[NWRD];
static __device__ unsigned g_B2[NN*NWRD];
static __device__ unsigned g_B3[NN*NWRD];

// ---------------- adjacency build ----------------
__global__ void k_zero_adj() {
    int i = blockIdx.x*256 + threadIdx.x;
    if (i < NN*NWRD) g_adj[i] = 0u;
}

__global__ void k_build_adj(const int* __restrict__ ei) {
    int e = blockIdx.x*256 + threadIdx.x;
    if (e >= 32768) return;
    int u = ei[e];
    int v = ei[32768 + e];
    atomicOr(&g_adj[u*NWRD + (v>>5)], 1u << (v & 31));
}

__global__ void k_post() {
    int i = blockIdx.x*256 + threadIdx.x;
    if (i >= NN) return;
    int cnt = 0;
    for (int w = 0; w < NWRD; w++) {
        unsigned m = g_adj[i*NWRD + w];
        while (m) {
            int b = __ffs(m) - 1;
            m &= m - 1;
            if (cnt < MAXD) g_nbr[i*MAXD + cnt] = w*32 + b;
            cnt++;
        }
    }
    g_deg[i] = cnt;
}

__global__ void k_scan() {
    __shared__ int A[NN], B[NN];
    int tid = threadIdx.x;
    for (int i = tid; i < NN; i += 1024) {
        int d = g_deg[i]; if (d > MAXD) d = MAXD;
        A[i] = d;
    }
    __syncthreads();
    int* cur = A; int* nxt = B;
    for (int off = 1; off < NN; off <<= 1) {
        for (int i = tid; i < NN; i += 1024) {
            int v = cur[i];
            if (i >= off) v += cur[i-off];
            nxt[i] = v;
        }
        __syncthreads();
        int* t = cur; cur = nxt; nxt = t;
    }
    for (int i = tid; i < NN; i += 1024) g_off[i+1] = cur[i];
    if (tid == 0) { g_off[0] = 0; g_nedges = cur[NN-1]; }
}

__global__ void k_fill_edges() {
    int i = blockIdx.x*256 + threadIdx.x;
    if (i >= NN) return;
    int o = g_off[i];
    int dg = g_deg[i]; if (dg > MAXD) dg = MAXD;
    for (int t = 0; t < dg; t++)
        g_ecol[o + t] = (unsigned short)g_nbr[i*MAXD + t];
}

// ---------------- V (entropy pre-term) ----------------
__global__ void k_V(const float* __restrict__ x) {
    __shared__ int   snb[MAXD];
    __shared__ int   sdeg;
    __shared__ float red[DD];
    int i = blockIdx.x;
    int d = threadIdx.x;
    if (d == 0) sdeg = g_deg[i];
    __syncthreads();
    int dg = sdeg; if (dg > MAXD) dg = MAXD;
    for (int t = d; t < dg; t += DD) snb[t] = g_nbr[i*MAXD + t];
    __syncthreads();
    float xi = x[i*DD + d];
    float ax = 0.f, axx = 0.f;
    for (int t = 0; t < dg; t++) {
        float v = x[snb[t]*DD + d];
        ax  += v;
        axx += v*v;
    }
    float tt = (float)sdeg*xi*xi - 2.f*xi*ax + axx;
    red[d] = tt*tt;
    __syncthreads();
    for (int s = DD/2; s > 0; s >>= 1) {
        if (d < s) red[d] += red[d+s];
        __syncthreads();
    }
    if (d == 0) g_V[i] = sqrtf(red[0]);
}

// ---------------- per-graph softmax -> ent, gamma ----------------
__global__ void k_softmax(const int* __restrict__ batch) {
    __shared__ float sV[NN];
    __shared__ float red[1024];
    __shared__ unsigned char sB[NN];
    __shared__ float gmax[GG], gsum[GG];
    int tid = threadIdx.x;
    for (int i = tid; i < NN; i += 1024) { sV[i] = g_V[i]; sB[i] = (unsigned char)batch[i]; }
    __syncthreads();
    for (int g = 0; g < GG; g++) {
        float m = -1e30f;
        for (int i = tid; i < NN; i += 1024) if (sB[i] == g) m = fmaxf(m, sV[i]);
        red[tid] = m; __syncthreads();
        for (int s = 512; s > 0; s >>= 1) { if (tid < s) red[tid] = fmaxf(red[tid], red[tid+s]); __syncthreads(); }
        if (tid == 0) gmax[g] = red[0];
        __syncthreads();
    }
    for (int i = tid; i < NN; i += 1024) sV[i] = expf(sV[i] - gmax[sB[i]]);
    __syncthreads();
    for (int g = 0; g < GG; g++) {
        float s = 0.f;
        for (int i = tid; i < NN; i += 1024) if (sB[i] == g) s += sV[i];
        red[tid] = s; __syncthreads();
        for (int st = 512; st > 0; st >>= 1) { if (tid < st) red[tid] += red[tid+st]; __syncthreads(); }
        if (tid == 0) gsum[g] = red[0];
        __syncthreads();
    }
    float acc = 0.f;
    for (int i = tid; i < NN; i += 1024) {
        float P = sV[i] / gsum[sB[i]];
        float e = (P == 0.f) ? 0.f : -P*logf(P);
        g_ent[i] = e;
        acc += e;
    }
    red[tid] = acc; __syncthreads();
    for (int s = 512; s > 0; s >>= 1) { if (tid < s) red[tid] += red[tid+s]; __syncthreads(); }
    if (tid == 0) g_gamma = red[0];
}

// ---------------- GIN layers ----------------
__global__ void k_agg1() {
    int i = blockIdx.x*256 + threadIdx.x;
    if (i >= NN) return;
    int dg = g_deg[i]; if (dg > MAXD) dg = MAXD;
    float a = g_ent[i];
    for (int t = 0; t < dg; t++) a += g_ent[g_nbr[i*MAXD + t]];
    g_a1[i] = a;
}

__global__ void k_lin1(const float* __restrict__ w11, const float* __restrict__ b11) {
    int idx = blockIdx.x*256 + threadIdx.x;
    if (idx >= NN*HH) return;
    int i = idx >> 7, c = idx & 127;
    float v = g_a1[i]*w11[c] + b11[c];
    g_z[idx] = v > 0.f ? v : 0.f;
}

__global__ void k_bnstats(const float* __restrict__ g, const float* __restrict__ be) {
    __shared__ float red[256];
    __shared__ float mu_s;
    int c = blockIdx.x, tid = threadIdx.x;
    float s = 0.f;
    for (int r = tid; r < NN; r += 256) s += g_z[r*HH + c];
    red[tid] = s; __syncthreads();
    for (int st = 128; st > 0; st >>= 1) { if (tid < st) red[tid] += red[tid+st]; __syncthreads(); }
    if (tid == 0) mu_s = red[0] / (float)NN;
    __syncthreads();
    float mu = mu_s;
    float s2 = 0.f;
    for (int r = tid; r < NN; r += 256) { float d = g_z[r*HH + c] - mu; s2 += d*d; }
    red[tid] = s2; __syncthreads();
    for (int st = 128; st > 0; st >>= 1) { if (tid < st) red[tid] += red[tid+st]; __syncthreads(); }
    if (tid == 0) {
        float var = red[0] / (float)NN;
        float inv = 1.f / sqrtf(var + 1e-5f);
        float sc  = g[c]*inv;
        g_sc[c] = sc;
        g_sh[c] = be[c] - mu*sc;
    }
}

__global__ void k_gemm2(const float* __restrict__ W, const float* __restrict__ b) {
    __shared__ float sA[16][HH];
    int r0 = blockIdx.x*16, c = threadIdx.x;
    float scc = g_sc[c], shc = g_sh[c];
    for (int rr = 0; rr < 16; rr++)
        sA[rr][c] = g_z[(r0+rr)*HH + c]*scc + shc;
    __syncthreads();
    float acc[16];
    float bc = b[c];
    #pragma unroll
    for (int rr = 0; rr < 16; rr++) acc[rr] = bc;
    for (int k = 0; k < HH; k++) {
        float w = W[k*HH + c];
        #pragma unroll
        for (int rr = 0; rr < 16; rr++) acc[rr] += sA[rr][k]*w;
    }
    for (int rr = 0; rr < 16; rr++) g_h[(r0+rr)*HH + c] = acc[rr];
}

__global__ void k_agg() {
    __shared__ int snb[MAXD];
    __shared__ int sdeg;
    int i = blockIdx.x, f = threadIdx.x;
    if (f == 0) sdeg = g_deg[i];
    __syncthreads();
    int dg = sdeg; if (dg > MAXD) dg = MAXD;
    for (int t = f; t < dg; t += HH) snb[t] = g_nbr[i*MAXD + t];
    __syncthreads();
    float acc = g_h[i*HH + f];
    for (int t = 0; t < dg; t++) acc += g_h[snb[t]*HH + f];
    g_u[i*HH + f] = acc;
}

__global__ void k_gemm_relu(const float* __restrict__ W, const float* __restrict__ b) {
    __shared__ float sA[16][HH];
    int r0 = blockIdx.x*16, c = threadIdx.x;
    for (int rr = 0; rr < 16; rr++)
        sA[rr][c] = g_u[(r0+rr)*HH + c];
    __syncthreads();
    float acc[16];
    float bc = b[c];
    #pragma unroll
    for (int rr = 0; rr < 16; rr++) acc[rr] = bc;
    for (int k = 0; k < HH; k++) {
        float w = W[k*HH + c];
        #pragma unroll
        for (int rr = 0; rr < 16; rr++) acc[rr] += sA[rr][k]*w;
    }
    for (int rr = 0; rr < 16; rr++) {
        float v = acc[rr];
        g_z[(r0+rr)*HH + c] = v > 0.f ? v : 0.f;
    }
}

__global__ void k_final(const float* __restrict__ w32, const float* __restrict__ b32) {
    int i = blockIdx.x*256 + threadIdx.x;
    if (i >= NN) return;
    float acc = b32[0];
    for (int k = 0; k < HH; k++)
        acc += (g_z[i*HH + k]*g_sc[k] + g_sh[k]) * w32[k];
    g_p[i] = 1.f / (1.f + expf(-acc));
}

// ---------------- speculative batched greedy ----------------
// Shared memory layout (byte offsets)
#define O_SKEY  0
#define O_DBL   (O_SKEY  + NN*8)          // scal[8]: E,Q,loss,gamma
#define O_PARTE (O_DBL   + 8*8)
#define O_PARTQ (O_PARTE + 32*8)
#define O_DEV   (O_PARTQ + 32*8)
#define O_DQV   (O_DEV   + 32*8)
#define O_SDUM  (O_DQV   + 32*8)
#define O_SENT  (O_SDUM  + NN*4)
#define O_SR    (O_SENT  + NN*4)
#define O_SOFF  (O_SR    + NN*4)          // (NN+4) ints
#define O_SWROW (O_SOFF  + (NN+4)*4)      // 32 warps x 64 words
#define O_SSEL  (O_SWROW + 32*NWRD*4)
#define O_SREJ  (O_SSEL  + NWRD*4)
#define O_SDZ   (O_SREJ  + NWRD*4)
#define O_SCAND (O_SDZ   + NWRD*4)
#define O_SPOS  (O_SCAND + 32*4)
#define O_SACC  (O_SPOS  + 32*4)
#define O_BM    (O_SACC  + 32*4)
#define O_WPRE  (O_BM    + 32*4)
#define O_CTRL  (O_WPRE  + 32*4)          // 8 ints: cursor, ws, total
#define O_SDG   (O_CTRL  + 8*4)
#define O_SEDGE (O_SDG   + NN*2)
#define SMEM_BYTES (O_SEDGE + 32768*2)

__global__ void k_sort_greedy() {
    extern __shared__ unsigned char SMB[];
    unsigned long long* skey = (unsigned long long*)(SMB + O_SKEY);
    double* scal  = (double*)(SMB + O_DBL);
    double* partE = (double*)(SMB + O_PARTE);
    double* partQ = (double*)(SMB + O_PARTQ);
    double* sdEv  = (double*)(SMB + O_DEV);
    double* sdQv  = (double*)(SMB + O_DQV);
    float*  sdum  = (float*)(SMB + O_SDUM);
    float*  sent  = (float*)(SMB + O_SENT);
    float*  sr    = (float*)(SMB + O_SR);
    int*    soff  = (int*)(SMB + O_SOFF);
    unsigned* swrow = (unsigned*)(SMB + O_SWROW);
    unsigned* ssel  = (unsigned*)(SMB + O_SSEL);
    unsigned* srej  = (unsigned*)(SMB + O_SREJ);
    unsigned* sdz   = (unsigned*)(SMB + O_SDZ);
    int*    scand = (int*)(SMB + O_SCAND);
    int*    spos  = (int*)(SMB + O_SPOS);
    int*    sacc  = (int*)(SMB + O_SACC);
    unsigned* bmask = (unsigned*)(SMB + O_BM);
    int*    wpre  = (int*)(SMB + O_WPRE);
    int*    ctrl  = (int*)(SMB + O_CTRL);
    short*  sdg   = (short*)(SMB + O_SDG);
    unsigned short* sedge = (unsigned short*)(SMB + O_SEDGE);

    int tid = threadIdx.x;
    int w = tid >> 5, lane = tid & 31;

    for (int i = tid; i < NN; i += 1024) {
        float pv = g_p[i];
        skey[i] = ((unsigned long long)(0xFFFFFFFFu - __float_as_uint(pv)) << 32) | (unsigned long long)i;
        sdum[i] = pv;
        sent[i] = g_ent[i];
        int dg = g_deg[i]; if (dg > MAXD) dg = MAXD;
        sdg[i] = (short)dg;
    }
    for (int i = tid; i <= NN; i += 1024) soff[i] = g_off[i];
    int nE = g_nedges;
    for (int e = tid; e < nE; e += 1024) sedge[e] = g_ecol[e];
    if (tid < NWRD) {
        ssel[tid] = 0u; srej[tid] = 0u;
        unsigned m = 0u;
        for (int b = 0; b < 32; b++) if (g_deg[tid*32 + b] == 0) m |= 1u << b;
        sdz[tid] = m;
    }
    if (tid == 0) { ctrl[0] = 0; scal[3] = (double)g_gamma; }
    __syncthreads();

    // r_u = neighbor-sum of d (same per-node ascending order as before)
    for (int i = tid; i < NN; i += 1024) {
        int b = soff[i], dg = sdg[i];
        float acc = 0.f;
        for (int t = 0; t < dg; t++) acc += sdum[sedge[b + t]];
        sr[i] = acc;
    }
    __syncthreads();

    // E0, Q0 partials (double)
    {
        double e = 0.0, q = 0.0;
        for (int i = tid; i < NN; i += 1024) {
            e += (double)sent[i] * (double)sdum[i];
            q += (double)sdum[i] * (double)sr[i];
        }
        for (int o = 16; o > 0; o >>= 1) {
            e += __shfl_down_sync(0xffffffffu, e, o);
            q += __shfl_down_sync(0xffffffffu, q, o);
        }
        if (lane == 0) { partE[w] = e; partQ[w] = q; }
    }
    __syncthreads();

    // bitonic sort ascending key (== descending p, ties by index ascending)
    for (int k = 2; k <= NN; k <<= 1) {
        for (int j = k >> 1; j > 0; j >>= 1) {
            for (int off = 0; off < NN; off += 1024) {
                int i = tid + off;
                int l = i ^ j;
                if (l > i) {
                    bool up = ((i & k) == 0);
                    unsigned long long a = skey[i], b = skey[l];
                    if ((a > b) == up) { skey[i] = b; skey[l] = a; }
                }
            }
            __syncthreads();
        }
    }

    // finalize E, Q, loss
    if (tid < 32) {
        double ee = partE[tid], qq = partQ[tid];
        for (int o = 16; o > 0; o >>= 1) {
            ee += __shfl_down_sync(0xffffffffu, ee, o);
            qq += __shfl_down_sync(0xffffffffu, qq, o);
        }
        if (tid == 0) {
            scal[0] = ee; scal[1] = qq;
            scal[2] = scal[3] - ee + qq;
            g_loss = (float)scal[2];
        }
    }
    __syncthreads();

    // ---- speculative loop ----
    while (true) {
        int cursor = ctrl[0];
        if (cursor >= NN) break;

        // gather: 1024-wide eligibility scan + ballot compaction
        int pos = cursor + tid;
        int node = -1, elig = 0;
        if (pos < NN) {
            node = (int)(skey[pos] & 0xFFFFFFFFull);
            int wd = node >> 5; unsigned bit = 1u << (node & 31);
            if (sdz[wd] & bit) {
                if (!(ssel[wd] & bit)) atomicOr(&ssel[wd], bit);   // isolated -> select (safe, idempotent)
            } else if (!((ssel[wd] | srej[wd]) & bit)) elig = 1;
        }
        unsigned bm = __ballot_sync(0xffffffffu, elig);
        if (lane == 0) bmask[w] = bm;
        if (tid < 32) sacc[tid] = 0;
        __syncthreads();
        if (tid < 32) {
            int c = __popc(bmask[tid]);
            int inc = c;
            for (int o = 1; o < 32; o <<= 1) {
                int nvl = __shfl_up_sync(0xffffffffu, inc, o);
                if (lane >= o) inc += nvl;
            }
            wpre[tid] = inc - c;
            if (tid == 31) ctrl[2] = inc;
        }
        __syncthreads();
        int total = ctrl[2];
        int count = total < 32 ? total : 32;
        if (elig) {
            int rank = wpre[w] + __popc(bm & ((1u << lane) - 1u));
            if (rank < 32) { scand[rank] = node; spos[rank] = pos; }
        }
        __syncthreads();

        // parallel speculative evals: warp w evaluates candidate w
        if (w < count) {
            int idx = scand[w];
            unsigned* srw = swrow + w*NWRD;
            for (int q = lane; q < NWRD; q += 32) srw[q] = g_adj[idx*NWRD + q];
            __syncwarp();
            int m = sdg[idx], cb = soff[idx];
            double dI = 1.0 - (double)sdum[idx];
            double dE = 0.0, dR = 0.0, rho0 = 0.0, dRho = 0.0;
            for (int k = lane; k < m; k += 32) {
                int u = sedge[cb + k];
                float duf = sdum[u];
                if (duf != 0.f) {
                    double du = -(double)duf;
                    dE   += du * (double)sent[u];
                    dR   += du * (double)sr[u];
                    rho0 += du;
                    int ub = soff[u], udg = sdg[u];
                    double rho = 0.0;
                    for (int j = 0; j < udg; j++) {
                        int v = sedge[ub + j];
                        if (v == idx) rho += dI;
                        else if ((srw[v>>5] >> (v & 31)) & 1u) rho -= (double)sdum[v];
                    }
                    dRho += du * rho;
                }
            }
            for (int o = 16; o > 0; o >>= 1) {
                dE   += __shfl_down_sync(0xffffffffu, dE,   o);
                dR   += __shfl_down_sync(0xffffffffu, dR,   o);
                rho0 += __shfl_down_sync(0xffffffffu, rho0, o);
                dRho += __shfl_down_sync(0xffffffffu, dRho, o);
            }
            if (lane == 0) {
                double dEt = dI * (double)sent[idx] + dE;
                double dQt = 2.0*(dI * (double)sr[idx] + dR) + dI*rho0 + dRho;
                double li = scal[3] - (scal[0] + dEt) + (scal[1] + dQt);
                sdEv[w] = dEt; sdQv[w] = dQt;
                sacc[w] = (li <= scal[2]) ? 1 : 0;
            }
        }
        __syncthreads();

        // decide: first acceptor wins
        if (tid == 0) {
            int ws = -1;
            for (int q = 0; q < count; q++) if (sacc[q]) { ws = q; break; }
            ctrl[1] = ws;
            if (ws >= 0) ctrl[0] = spos[ws] + 1;
            else ctrl[0] = (count > 0) ? (spos[count-1] + 1) : (cursor + 1024);
        }
        __syncthreads();

        // commit by warp 0 (identical order/numerics to sequential version)
        int ws = ctrl[1];
        if (ws >= 0 && w == 0) {
            int idx = scand[ws];
            unsigned* srw = swrow + ws*NWRD;
            int m = sdg[idx], cb = soff[idx];
            float dIf = (float)(1.0 - (double)sdum[idx]);
            if (lane == 0) {
                scal[0] += sdEv[ws];
                scal[1] += sdQv[ws];
                ssel[idx>>5] |= 1u << (idx & 31);
            }
            __syncwarp();
            for (int k = lane; k < m; k += 32) sr[sedge[cb + k]] += dIf;
            __syncwarp();
            for (int k = 0; k < m; k++) {
                int u = sedge[cb + k];
                float duf = sdum[u];
                if (duf != 0.f) {
                    int ub = soff[u], udg = sdg[u];
                    for (int j = lane; j < udg; j += 32) sr[sedge[ub + j]] -= duf;
                }
                __syncwarp();
            }
            for (int k = lane; k < m; k += 32) sdum[sedge[cb + k]] = 0.f;
            if (lane == 0) sdum[idx] = 1.f;
            for (int q = lane; q < NWRD; q += 32) srej[q] |= srw[q];
        }
        __syncthreads();
    }
    for (int q = tid; q < NWRD; q += 1024) g_sel[q] = ssel[q];
}

// ---------------- boolean adjacency powers ----------------
__global__ void k_bool(int phase) {
    __shared__ int snb[MAXD];
    __shared__ int sdeg;
    int i = blockIdx.x, w = threadIdx.x;
    if (w == 0) sdeg = g_deg[i];
    __syncthreads();
    int dg = sdeg; if (dg > MAXD) dg = MAXD;
    for (int t = w; t < dg; t += NWRD) snb[t] = g_nbr[i*MAXD + t];
    __syncthreads();
    unsigned acc = 0u;
    if (phase == 0) {
        for (int t = 0; t < dg; t++) acc |= g_adj[snb[t]*NWRD + w];
        g_B2[i*NWRD + w] = acc;
    } else {
        for (int t = 0; t < dg; t++) acc |= g_B2[snb[t]*NWRD + w];
        g_B3[i*NWRD + w] = acc;
    }
}

// ---------------- output assembly ----------------
__global__ void k_out(float* __restrict__ out, const float* __restrict__ x,
                      const int* __restrict__ batch, int out_size) {
    const int XP  = NN*DD;
    const int AE  = XP + NN*NN;
    const int SE  = AE + NN;
    const int BE  = SE + NN;
    int idx = blockIdx.x*256 + threadIdx.x;
    if (idx >= out_size) return;
    if (idx < XP) {
        int i = idx >> 8;
        bool s = (g_sel[i>>5] >> (i & 31)) & 1u;
        out[idx] = s ? x[idx] : 0.f;
    } else if (idx < AE) {
        int e = idx - XP;
        int i = e >> 11, j = e & 2047;
        unsigned b = ((g_B2[i*NWRD + (j>>5)] | g_B3[i*NWRD + (j>>5)]) >> (j & 31)) & 1u;
        bool si = (g_sel[i>>5] >> (i & 31)) & 1u;
        bool sj = (g_sel[j>>5] >> (j & 31)) & 1u;
        out[idx] = ((i != j) && b && si && sj) ? 1.f : 0.f;
    } else if (idx < SE) {
        int i = idx - AE;
        out[idx] = ((g_sel[i>>5] >> (i & 31)) & 1u) ? 1.f : 0.f;
    } else if (idx < BE) {
        int i = idx - SE;
        out[idx] = ((g_sel[i>>5] >> (i & 31)) & 1u) ? (float)batch[i] : -1.f;
    } else {
        out[idx] = g_loss;
    }
}

// ---------------- launch ----------------
extern "C" void kernel_launch(void* const* d_in, const int* in_sizes, int n_in,
                              void* d_out, int out_size) {
    const float* x   = (const float*)d_in[0];
    const int*   ei  = (const int*)  d_in[1];
    const int*   bat = (const int*)  d_in[2];
    const float* w11 = (const float*)d_in[3];
    const float* b11 = (const float*)d_in[4];
    const float* g1  = (const float*)d_in[5];
    const float* be1 = (const float*)d_in[6];
    const float* w12 = (const float*)d_in[7];
    const float* b12 = (const float*)d_in[8];
    const float* w21 = (const float*)d_in[9];
    const float* b21 = (const float*)d_in[10];
    const float* g2  = (const float*)d_in[11];
    const float* be2 = (const float*)d_in[12];
    const float* w22 = (const float*)d_in[13];
    const float* b22 = (const float*)d_in[14];
    const float* w31 = (const float*)d_in[15];
    const float* b31 = (const float*)d_in[16];
    const float* g3  = (const float*)d_in[17];
    const float* be3 = (const float*)d_in[18];
    const float* w32 = (const float*)d_in[19];
    const float* b32 = (const float*)d_in[20];
    float* out = (float*)d_out;

    static int smem_set = 0;
    if (!smem_set) {
        cudaFuncSetAttribute(k_sort_greedy, cudaFuncAttributeMaxDynamicSharedMemorySize, SMEM_BYTES);
        smem_set = 1;
    }

    // adjacency + CSR
    k_zero_adj<<<(NN*NWRD + 255)/256, 256>>>();
    k_build_adj<<<(32768 + 255)/256, 256>>>(ei);
    k_post<<<NN/256, 256>>>();
    k_scan<<<1, 1024>>>();
    k_fill_edges<<<NN/256, 256>>>();

    // entropy
    k_V<<<NN, DD>>>(x);
    k_softmax<<<1, 1024>>>(bat);

    // GIN layer 1
    k_agg1<<<NN/256, 256>>>();
    k_lin1<<<(NN*HH + 255)/256, 256>>>(w11, b11);
    k_bnstats<<<HH, 256>>>(g1, be1);
    k_gemm2<<<NN/16, HH>>>(w12, b12);

    // GIN layer 2
    k_agg<<<NN, HH>>>();
    k_gemm_relu<<<NN/16, HH>>>(w21, b21);
    k_bnstats<<<HH, 256>>>(g2, be2);
    k_gemm2<<<NN/16, HH>>>(w22, b22);

    // GIN layer 3
    k_agg<<<NN, HH>>>();
    k_gemm_relu<<<NN/16, HH>>>(w31, b31);
    k_bnstats<<<HH, 256>>>(g3, be3);
    k_final<<<NN/256, 256>>>(w32, b32);

    // speculative greedy (computes loss internally)
    k_sort_greedy<<<1, 1024, SMEM_BYTES>>>();

    // boolean A^2, A^3
    k_bool<<<NN, NWRD>>>(0);
    k_bool<<<NN, NWRD>>>(1);

    // outputs
    k_out<<<(out_size + 255)/256, 256>>>(out, x, bat, out_size);
}

// round 5
// speedup vs baseline: 3.5947x; 3.5947x over previous
#include <cuda_runtime.h>
#include <math.h>

#define NN 2048
#define DD 256
#define HH 128
#define GG 8
#define MAXD 128
#define NWRD 64     // 32-bit words per adjacency row (2048 bits)
#define TCAP 32     // max stored triangle pairs per node

// ---------------- device scratch (static, no runtime allocation) ----------------
static __device__ unsigned g_adj[NN*NWRD];
static __device__ int      g_deg[NN];
static __device__ int      g_nbr[NN*MAXD];
static __device__ int      g_off[NN+1];
static __device__ int      g_nedges;
static __device__ unsigned short g_ecol[32768];   // CSR columns (u16)
static __device__ int      g_tricnt[NN];
static __device__ unsigned g_tri[NN*TCAP];        // packed (u<<16)|v adjacent-neighbor pairs
static __device__ float    g_V[NN];
static __device__ float    g_ent[NN];
static __device__ float    g_p[NN];
static __device__ float    g_a1[NN];
static __device__ float    g_u[NN*HH];
static __device__ float    g_z[NN*HH];
static __device__ float    g_h[NN*HH];
static __device__ float    g_sc[HH];
static __device__ float    g_sh[HH];
static __device__ float    g_gamma;
static __device__ float    g_loss;
static __device__ unsigned g_sel[NWRD];
static __device__ unsigned g_B2[NN*NWRD];
static __device__ unsigned g_B3[NN*NWRD];

// ---------------- adjacency build ----------------
__global__ void k_zero_adj() {
    int i = blockIdx.x*256 + threadIdx.x;
    if (i < NN*NWRD) g_adj[i] = 0u;
}

__global__ void k_build_adj(const int* __restrict__ ei) {
    int e = blockIdx.x*256 + threadIdx.x;
    if (e >= 32768) return;
    int u = ei[e];
    int v = ei[32768 + e];
    atomicOr(&g_adj[u*NWRD + (v>>5)], 1u << (v & 31));
}

__global__ void k_post() {
    int i = blockIdx.x*256 + threadIdx.x;
    if (i >= NN) return;
    int cnt = 0;
    for (int w = 0; w < NWRD; w++) {
        unsigned m = g_adj[i*NWRD + w];
        while (m) {
            int b = __ffs(m) - 1;
            m &= m - 1;
            if (cnt < MAXD) g_nbr[i*MAXD + cnt] = w*32 + b;
            cnt++;
        }
    }
    g_deg[i] = cnt;
}

__global__ void k_scan() {
    __shared__ int A[NN], B[NN];
    int tid = threadIdx.x;
    for (int i = tid; i < NN; i += 1024) {
        int d = g_deg[i]; if (d > MAXD) d = MAXD;
        A[i] = d;
    }
    __syncthreads();
    int* cur = A; int* nxt = B;
    for (int off = 1; off < NN; off <<= 1) {
        for (int i = tid; i < NN; i += 1024) {
            int v = cur[i];
            if (i >= off) v += cur[i-off];
            nxt[i] = v;
        }
        __syncthreads();
        int* t = cur; cur = nxt; nxt = t;
    }
    for (int i = tid; i < NN; i += 1024) g_off[i+1] = cur[i];
    if (tid == 0) { g_off[0] = 0; g_nedges = cur[NN-1]; }
}

__global__ void k_fill_edges() {
    int i = blockIdx.x*256 + threadIdx.x;
    if (i >= NN) return;
    int o = g_off[i];
    int dg = g_deg[i]; if (dg > MAXD) dg = MAXD;
    for (int t = 0; t < dg; t++)
        g_ecol[o + t] = (unsigned short)g_nbr[i*MAXD + t];
}

// ---------------- triangle pair lists (graph-static) ----------------
// For node x: all pairs (u,v), u=nb[k], v=nb[l], k<l, with u~v.
// Deterministic order: k-major, l-ascending.
__global__ void k_tri() {
    int warp = (blockIdx.x*256 + threadIdx.x) >> 5;
    int lane = threadIdx.x & 31;
    if (warp >= NN) return;
    int x = warp;
    int base = g_off[x];
    int m = g_off[x+1] - base;
    int cnt = 0;
    for (int k = 0; k + 1 < m; k++) {
        unsigned u = g_ecol[base + k];
        const unsigned* rowu = &g_adj[u*NWRD];
        for (int l0 = k + 1; l0 < m; l0 += 32) {
            int l = l0 + lane;
            int ok = 0;
            unsigned v = 0;
            if (l < m) {
                v = g_ecol[base + l];
                ok = (rowu[v>>5] >> (v & 31)) & 1;
            }
            unsigned bal = __ballot_sync(0xffffffffu, ok);
            if (ok) {
                int pos = cnt + __popc(bal & ((1u << lane) - 1u));
                if (pos < TCAP) g_tri[x*TCAP + pos] = (u << 16) | v;
            }
            cnt += __popc(bal);
        }
    }
    if (lane == 0) g_tricnt[x] = cnt < TCAP ? cnt : TCAP;
}

// ---------------- V (entropy pre-term) ----------------
__global__ void k_V(const float* __restrict__ x) {
    __shared__ int   snb[MAXD];
    __shared__ int   sdeg;
    __shared__ float red[DD];
    int i = blockIdx.x;
    int d = threadIdx.x;
    if (d == 0) sdeg = g_deg[i];
    __syncthreads();
    int dg = sdeg; if (dg > MAXD) dg = MAXD;
    for (int t = d; t < dg; t += DD) snb[t] = g_nbr[i*MAXD + t];
    __syncthreads();
    float xi = x[i*DD + d];
    float ax = 0.f, axx = 0.f;
    for (int t = 0; t < dg; t++) {
        float v = x[snb[t]*DD + d];
        ax  += v;
        axx += v*v;
    }
    float tt = (float)sdeg*xi*xi - 2.f*xi*ax + axx;
    red[d] = tt*tt;
    __syncthreads();
    for (int s = DD/2; s > 0; s >>= 1) {
        if (d < s) red[d] += red[d+s];
        __syncthreads();
    }
    if (d == 0) g_V[i] = sqrtf(red[0]);
}

// ---------------- per-graph softmax -> ent, gamma ----------------
__global__ void k_softmax(const int* __restrict__ batch) {
    __shared__ float sV[NN];
    __shared__ float red[1024];
    __shared__ unsigned char sB[NN];
    __shared__ float gmax[GG], gsum[GG];
    int tid = threadIdx.x;
    for (int i = tid; i < NN; i += 1024) { sV[i] = g_V[i]; sB[i] = (unsigned char)batch[i]; }
    __syncthreads();
    for (int g = 0; g < GG; g++) {
        float m = -1e30f;
        for (int i = tid; i < NN; i += 1024) if (sB[i] == g) m = fmaxf(m, sV[i]);
        red[tid] = m; __syncthreads();
        for (int s = 512; s > 0; s >>= 1) { if (tid < s) red[tid] = fmaxf(red[tid], red[tid+s]); __syncthreads(); }
        if (tid == 0) gmax[g] = red[0];
        __syncthreads();
    }
    for (int i = tid; i < NN; i += 1024) sV[i] = expf(sV[i] - gmax[sB[i]]);
    __syncthreads();
    for (int g = 0; g < GG; g++) {
        float s = 0.f;
        for (int i = tid; i < NN; i += 1024) if (sB[i] == g) s += sV[i];
        red[tid] = s; __syncthreads();
        for (int st = 512; st > 0; st >>= 1) { if (tid < st) red[tid] += red[tid+st]; __syncthreads(); }
        if (tid == 0) gsum[g] = red[0];
        __syncthreads();
    }
    float acc = 0.f;
    for (int i = tid; i < NN; i += 1024) {
        float P = sV[i] / gsum[sB[i]];
        float e = (P == 0.f) ? 0.f : -P*logf(P);
        g_ent[i] = e;
        acc += e;
    }
    red[tid] = acc; __syncthreads();
    for (int s = 512; s > 0; s >>= 1) { if (tid < s) red[tid] += red[tid+s]; __syncthreads(); }
    if (tid == 0) g_gamma = red[0];
}

// ---------------- GIN layers ----------------
__global__ void k_agg1() {
    int i = blockIdx.x*256 + threadIdx.x;
    if (i >= NN) return;
    int dg = g_deg[i]; if (dg > MAXD) dg = MAXD;
    float a = g_ent[i];
    for (int t = 0; t < dg; t++) a += g_ent[g_nbr[i*MAXD + t]];
    g_a1[i] = a;
}

__global__ void k_lin1(const float* __restrict__ w11, const float* __restrict__ b11) {
    int idx = blockIdx.x*256 + threadIdx.x;
    if (idx >= NN*HH) return;
    int i = idx >> 7, c = idx & 127;
    float v = g_a1[i]*w11[c] + b11[c];
    g_z[idx] = v > 0.f ? v : 0.f;
}

__global__ void k_bnstats(const float* __restrict__ g, const float* __restrict__ be) {
    __shared__ float red[256];
    __shared__ float mu_s;
    int c = blockIdx.x, tid = threadIdx.x;
    float s = 0.f;
    for (int r = tid; r < NN; r += 256) s += g_z[r*HH + c];
    red[tid] = s; __syncthreads();
    for (int st = 128; st > 0; st >>= 1) { if (tid < st) red[tid] += red[tid+st]; __syncthreads(); }
    if (tid == 0) mu_s = red[0] / (float)NN;
    __syncthreads();
    float mu = mu_s;
    float s2 = 0.f;
    for (int r = tid; r < NN; r += 256) { float d = g_z[r*HH + c] - mu; s2 += d*d; }
    red[tid] = s2; __syncthreads();
    for (int st = 128; st > 0; st >>= 1) { if (tid < st) red[tid] += red[tid+st]; __syncthreads(); }
    if (tid == 0) {
        float var = red[0] / (float)NN;
        float inv = 1.f / sqrtf(var + 1e-5f);
        float sc  = g[c]*inv;
        g_sc[c] = sc;
        g_sh[c] = be[c] - mu*sc;
    }
}

__global__ void k_gemm2(const float* __restrict__ W, const float* __restrict__ b) {
    __shared__ float sA[16][HH];
    int r0 = blockIdx.x*16, c = threadIdx.x;
    float scc = g_sc[c], shc = g_sh[c];
    for (int rr = 0; rr < 16; rr++)
        sA[rr][c] = g_z[(r0+rr)*HH + c]*scc + shc;
    __syncthreads();
    float acc[16];
    float bc = b[c];
    #pragma unroll
    for (int rr = 0; rr < 16; rr++) acc[rr] = bc;
    for (int k = 0; k < HH; k++) {
        float w = W[k*HH + c];
        #pragma unroll
        for (int rr = 0; rr < 16; rr++) acc[rr] += sA[rr][k]*w;
    }
    for (int rr = 0; rr < 16; rr++) g_h[(r0+rr)*HH + c] = acc[rr];
}

__global__ void k_agg() {
    __shared__ int snb[MAXD];
    __shared__ int sdeg;
    int i = blockIdx.x, f = threadIdx.x;
    if (f == 0) sdeg = g_deg[i];
    __syncthreads();
    int dg = sdeg; if (dg > MAXD) dg = MAXD;
    for (int t = f; t < dg; t += HH) snb[t] = g_nbr[i*MAXD + t];
    __syncthreads();
    float acc = g_h[i*HH + f];
    for (int t = 0; t < dg; t++) acc += g_h[snb[t]*HH + f];
    g_u[i*HH + f] = acc;
}

__global__ void k_gemm_relu(const float* __restrict__ W, const float* __restrict__ b) {
    __shared__ float sA[16][HH];
    int r0 = blockIdx.x*16, c = threadIdx.x;
    for (int rr = 0; rr < 16; rr++)
        sA[rr][c] = g_u[(r0+rr)*HH + c];
    __syncthreads();
    float acc[16];
    float bc = b[c];
    #pragma unroll
    for (int rr = 0; rr < 16; rr++) acc[rr] = bc;
    for (int k = 0; k < HH; k++) {
        float w = W[k*HH + c];
        #pragma unroll
        for (int rr = 0; rr < 16; rr++) acc[rr] += sA[rr][k]*w;
    }
    for (int rr = 0; rr < 16; rr++) {
        float v = acc[rr];
        g_z[(r0+rr)*HH + c] = v > 0.f ? v : 0.f;
    }
}

__global__ void k_final(const float* __restrict__ w32, const float* __restrict__ b32) {
    int i = blockIdx.x*256 + threadIdx.x;
    if (i >= NN) return;
    float acc = b32[0];
    for (int k = 0; k < HH; k++)
        acc += (g_z[i*HH + k]*g_sc[k] + g_sh[k]) * w32[k];
    g_p[i] = 1.f / (1.f + expf(-acc));
}

// ---------------- sort + sequential greedy with O(deg) eval ----------------
// Shared layout (bytes)
#define T_SKEY  0                         // NN*8
#define T_SDUM  (T_SKEY  + NN*8)          // NN*4
#define T_SENT  (T_SDUM  + NN*4)          // NN*4
#define T_SR    (T_SENT  + NN*4)          // NN*4
#define T_SOFF  (T_SR    + NN*4)          // (NN+4)*4
#define T_SEDGE (T_SOFF  + (NN+4)*4)      // 32768*2
#define T_PARTE (T_SEDGE + 32768*2)       // 32*8
#define T_PARTQ (T_PARTE + 32*8)          // 32*8
#define T_SSEL  (T_PARTQ + 32*8)          // NWRD*4
#define T_SREJ  (T_SSEL  + NWRD*4)
#define T_SDZ   (T_SREJ  + NWRD*4)
#define SMEM_BYTES (T_SDZ + NWRD*4)

__global__ void k_sort_greedy() {
    extern __shared__ unsigned char SMB[];
    unsigned long long* skey = (unsigned long long*)(SMB + T_SKEY);
    float*  sdum  = (float*)(SMB + T_SDUM);
    float*  sent  = (float*)(SMB + T_SENT);
    float*  sr    = (float*)(SMB + T_SR);
    int*    soff  = (int*)(SMB + T_SOFF);
    unsigned short* sedge = (unsigned short*)(SMB + T_SEDGE);
    double* partE = (double*)(SMB + T_PARTE);
    double* partQ = (double*)(SMB + T_PARTQ);
    unsigned* ssel = (unsigned*)(SMB + T_SSEL);
    unsigned* srej = (unsigned*)(SMB + T_SREJ);
    unsigned* sdz  = (unsigned*)(SMB + T_SDZ);

    int tid = threadIdx.x;
    for (int i = tid; i < NN; i += 1024) {
        float pv = g_p[i];
        skey[i] = ((unsigned long long)(0xFFFFFFFFu - __float_as_uint(pv)) << 32) | (unsigned long long)i;
        sdum[i] = pv;
        sent[i] = g_ent[i];
    }
    for (int i = tid; i <= NN; i += 1024) soff[i] = g_off[i];
    {
        int nE = g_nedges;
        for (int e = tid; e < nE; e += 1024) sedge[e] = g_ecol[e];
    }
    if (tid < NWRD) {
        ssel[tid] = 0u; srej[tid] = 0u;
        unsigned m = 0u;
        for (int b = 0; b < 32; b++) if (g_deg[tid*32 + b] == 0) m |= 1u << b;
        sdz[tid] = m;
    }
    __syncthreads();

    // r_u = neighbor-sum of d (ascending neighbor order)
    for (int i = tid; i < NN; i += 1024) {
        int b = soff[i], dg = soff[i+1] - b;
        float acc = 0.f;
        for (int t = 0; t < dg; t++) acc += sdum[sedge[b + t]];
        sr[i] = acc;
    }
    __syncthreads();

    // E0, Q0 partials (double)
    {
        double e = 0.0, q = 0.0;
        for (int i = tid; i < NN; i += 1024) {
            e += (double)sent[i] * (double)sdum[i];
            q += (double)sdum[i] * (double)sr[i];
        }
        for (int o = 16; o > 0; o >>= 1) {
            e += __shfl_down_sync(0xffffffffu, e, o);
            q += __shfl_down_sync(0xffffffffu, q, o);
        }
        if ((tid & 31) == 0) { partE[tid >> 5] = e; partQ[tid >> 5] = q; }
    }
    __syncthreads();

    // bitonic sort ascending key (== descending p, ties by index ascending)
    for (int k = 2; k <= NN; k <<= 1) {
        for (int j = k >> 1; j > 0; j >>= 1) {
            for (int off = 0; off < NN; off += 1024) {
                int i = tid + off;
                int l = i ^ j;
                if (l > i) {
                    bool up = ((i & k) == 0);
                    unsigned long long a = skey[i], b = skey[l];
                    if ((a > b) == up) { skey[i] = b; skey[l] = a; }
                }
            }
            __syncthreads();
        }
    }

    if (tid >= 32) return;   // greedy runs on warp 0 only

    double E, Q;
    {
        double ee = partE[tid], qq = partQ[tid];
        for (int o = 16; o > 0; o >>= 1) {
            ee += __shfl_down_sync(0xffffffffu, ee, o);
            qq += __shfl_down_sync(0xffffffffu, qq, o);
        }
        E = __shfl_sync(0xffffffffu, ee, 0);
        Q = __shfl_sync(0xffffffffu, qq, 0);
    }
    double gamma = (double)g_gamma;
    double lossd = gamma - E + Q;
    if (tid == 0) g_loss = (float)lossd;

    int t = 0;
    while (true) {
        int idx = -1;
        if (tid == 0) {
            while (t < NN) {
                int cand = (int)(skey[t] & 0xFFFFFFFFull);
                int w = cand >> 5; unsigned bit = 1u << (cand & 31);
                if (sdz[w] & bit)              { ssel[w] |= bit; t++; continue; } // isolated -> select
                if ((ssel[w] | srej[w]) & bit) { t++; continue; }                  // ineligible -> skip
                idx = cand; break;
            }
            t++;
        }
        idx = __shfl_sync(0xffffffffu, idx, 0);
        if (idx < 0) break;

        int base = soff[idx];
        int m = soff[idx+1] - base;
        int tcnt = g_tricnt[idx];
        double dI = 1.0 - (double)sdum[idx];

        // O(deg) eval: S1 = sum d_u*ent_u, S2 = sum d_u*r_u, S3 = sum d_u,
        //              S4 = sum over adjacent-neighbor pairs d_u*d_v
        double S1 = 0.0, S2 = 0.0, S3 = 0.0, S4 = 0.0;
        for (int k = tid; k < m; k += 32) {
            int u = sedge[base + k];
            double du = (double)sdum[u];
            S1 += du * (double)sent[u];
            S2 += du * (double)sr[u];
            S3 += du;
        }
        for (int q = tid; q < tcnt; q += 32) {
            unsigned pr = g_tri[idx*TCAP + q];
            S4 += (double)sdum[pr >> 16] * (double)sdum[pr & 0xFFFF];
        }
        for (int o = 16; o > 0; o >>= 1) {
            S1 += __shfl_down_sync(0xffffffffu, S1, o);
            S2 += __shfl_down_sync(0xffffffffu, S2, o);
            S3 += __shfl_down_sync(0xffffffffu, S3, o);
            S4 += __shfl_down_sync(0xffffffffu, S4, o);
        }
        int accept = 0;
        double dEt = 0.0, dQt = 0.0;
        if (tid == 0) {
            dEt = dI * (double)sent[idx] - S1;
            dQt = 2.0*(dI * (double)sr[idx] - S2) - 2.0*dI*S3 + 2.0*S4;
            double li = gamma - (E + dEt) + (Q + dQt);
            accept = (li <= lossd) ? 1 : 0;
        }
        accept = __shfl_sync(0xffffffffu, accept, 0);
        if (accept) {
            dEt = __shfl_sync(0xffffffffu, dEt, 0);
            dQt = __shfl_sync(0xffffffffu, dQt, 0);
            E += dEt; Q += dQt;
            if (tid == 0) ssel[idx>>5] |= 1u << (idx & 31);
            float fdI = (float)dI;
            for (int k = tid; k < m; k += 32) sr[sedge[base + k]] += fdI;
            __syncwarp();
            for (int k = 0; k < m; k++) {
                int u = sedge[base + k];
                float duf = sdum[u];
                if (duf != 0.f) {
                    int ub = soff[u], um = soff[u+1] - ub;
                    for (int j = tid; j < um; j += 32) sr[sedge[ub + j]] -= duf;
                }
                __syncwarp();
            }
            for (int k = tid; k < m; k += 32) sdum[sedge[base + k]] = 0.f;
            if (tid == 0) sdum[idx] = 1.f;
            for (int q = tid; q < NWRD; q += 32) srej[q] |= g_adj[idx*NWRD + q];
            __syncwarp();
        }
    }
    for (int q = tid; q < NWRD; q += 32) g_sel[q] = ssel[q];
}

// ---------------- boolean adjacency powers ----------------
__global__ void k_bool(int phase) {
    __shared__ int snb[MAXD];
    __shared__ int sdeg;
    int i = blockIdx.x, w = threadIdx.x;
    if (w == 0) sdeg = g_deg[i];
    __syncthreads();
    int dg = sdeg; if (dg > MAXD) dg = MAXD;
    for (int t = w; t < dg; t += NWRD) snb[t] = g_nbr[i*MAXD + t];
    __syncthreads();
    unsigned acc = 0u;
    if (phase == 0) {
        for (int t = 0; t < dg; t++) acc |= g_adj[snb[t]*NWRD + w];
        g_B2[i*NWRD + w] = acc;
    } else {
        for (int t = 0; t < dg; t++) acc |= g_B2[snb[t]*NWRD + w];
        g_B3[i*NWRD + w] = acc;
    }
}

// ---------------- output assembly ----------------
__global__ void k_out(float* __restrict__ out, const float* __restrict__ x,
                      const int* __restrict__ batch, int out_size) {
    const int XP  = NN*DD;
    const int AE  = XP + NN*NN;
    const int SE  = AE + NN;
    const int BE  = SE + NN;
    int idx = blockIdx.x*256 + threadIdx.x;
    if (idx >= out_size) return;
    if (idx < XP) {
        int i = idx >> 8;
        bool s = (g_sel[i>>5] >> (i & 31)) & 1u;
        out[idx] = s ? x[idx] : 0.f;
    } else if (idx < AE) {
        int e = idx - XP;
        int i = e >> 11, j = e & 2047;
        unsigned b = ((g_B2[i*NWRD + (j>>5)] | g_B3[i*NWRD + (j>>5)]) >> (j & 31)) & 1u;
        bool si = (g_sel[i>>5] >> (i & 31)) & 1u;
        bool sj = (g_sel[j>>5] >> (j & 31)) & 1u;
        out[idx] = ((i != j) && b && si && sj) ? 1.f : 0.f;
    } else if (idx < SE) {
        int i = idx - AE;
        out[idx] = ((g_sel[i>>5] >> (i & 31)) & 1u) ? 1.f : 0.f;
    } else if (idx < BE) {
        int i = idx - SE;
        out[idx] = ((g_sel[i>>5] >> (i & 31)) & 1u) ? (float)batch[i] : -1.f;
    } else {
        out[idx] = g_loss;
    }
}

// ---------------- launch ----------------
extern "C" void kernel_launch(void* const* d_in, const int* in_sizes, int n_in,
                              void* d_out, int out_size) {
    const float* x   = (const float*)d_in[0];
    const int*   ei  = (const int*)  d_in[1];
    const int*   bat = (const int*)  d_in[2];
    const float* w11 = (const float*)d_in[3];
    const float* b11 = (const float*)d_in[4];
    const float* g1  = (const float*)d_in[5];
    const float* be1 = (const float*)d_in[6];
    const float* w12 = (const float*)d_in[7];
    const float* b12 = (const float*)d_in[8];
    const float* w21 = (const float*)d_in[9];
    const float* b21 = (const float*)d_in[10];
    const float* g2  = (const float*)d_in[11];
    const float* be2 = (const float*)d_in[12];
    const float* w22 = (const float*)d_in[13];
    const float* b22 = (const float*)d_in[14];
    const float* w31 = (const float*)d_in[15];
    const float* b31 = (const float*)d_in[16];
    const float* g3  = (const float*)d_in[17];
    const float* be3 = (const float*)d_in[18];
    const float* w32 = (const float*)d_in[19];
    const float* b32 = (const float*)d_in[20];
    float* out = (float*)d_out;

    cudaFuncSetAttribute(k_sort_greedy, cudaFuncAttributeMaxDynamicSharedMemorySize, SMEM_BYTES);

    // adjacency + CSR + triangles
    k_zero_adj<<<(NN*NWRD + 255)/256, 256>>>();
    k_build_adj<<<(32768 + 255)/256, 256>>>(ei);
    k_post<<<NN/256, 256>>>();
    k_scan<<<1, 1024>>>();
    k_fill_edges<<<NN/256, 256>>>();
    k_tri<<<NN/8, 256>>>();

    // entropy
    k_V<<<NN, DD>>>(x);
    k_softmax<<<1, 1024>>>(bat);

    // GIN layer 1
    k_agg1<<<NN/256, 256>>>();
    k_lin1<<<(NN*HH + 255)/256, 256>>>(w11, b11);
    k_bnstats<<<HH, 256>>>(g1, be1);
    k_gemm2<<<NN/16, HH>>>(w12, b12);

    // GIN layer 2
    k_agg<<<NN, HH>>>();
    k_gemm_relu<<<NN/16, HH>>>(w21, b21);
    k_bnstats<<<HH, 256>>>(g2, be2);
    k_gemm2<<<NN/16, HH>>>(w22, b22);

    // GIN layer 3
    k_agg<<<NN, HH>>>();
    k_gemm_relu<<<NN/16, HH>>>(w31, b31);
    k_bnstats<<<HH, 256>>>(g3, be3);
    k_final<<<NN/256, 256>>>(w32, b32);

    // sequential greedy with O(deg) evals (computes loss internally)
    k_sort_greedy<<<1, 1024, SMEM_BYTES>>>();

    // boolean A^2, A^3
    k_bool<<<NN, NWRD>>>(0);
    k_bool<<<NN, NWRD>>>(1);

    // outputs
    k_out<<<(out_size + 255)/256, 256>>>(out, x, bat, out_size);
}